// round 4
// baseline (speedup 1.0000x reference)
#include <cuda_runtime.h>

#define BB   4
#define NTOK 4096
#define CC   256
#define NHH  8
#define HDD  32
#define LL   9
#define PP   64
#define TT   4096

// ---------------- scratch ----------------
__device__ float g_qraw [BB*NTOK*CC];
__device__ float g_kvraw[BB*NTOK*2*CC];
__device__ float g_qs   [BB*NTOK*CC];
__device__ float g_qn   [BB*NTOK*CC];
__device__ float g_kn   [BB*NTOK*CC];
__device__ float g_v    [BB*NTOK*CC];
__device__ float g_xs   [BB*NTOK*CC];
__device__ float g_pln  [BB*PP*CC];
__device__ float g_kpT  [BB*NHH*HDD*PP];   // [b][h][d][p]
__device__ float g_vpl  [BB*NHH*PP*HDD];   // [b][h][p][d]
__device__ float g_cpb  [TT*NHH];
__device__ float g_pb   [NTOK*NHH*PP];     // [n][h][p]
__device__ float g_att  [BB*NTOK*CC];

// ---------------- packed f32x2 helpers ----------------
__device__ __forceinline__ void fma2(unsigned long long &d,
                                     unsigned long long a, unsigned long long b){
    asm("fma.rn.f32x2 %0, %1, %2, %0;" : "+l"(d) : "l"(a), "l"(b));
}
__device__ __forceinline__ float2 u2f(unsigned long long u){
    float2 f; asm("mov.b64 {%0, %1}, %2;" : "=f"(f.x), "=f"(f.y) : "l"(u)); return f;
}
__device__ __forceinline__ unsigned long long dl(double d){
    return __double_as_longlong(d);
}

// ---------------- GEMM: Y[m,o] = sum_k A[m,k]*W[o,k] + bias[o] ----------------
// 128x128 tile, 256 threads. Accumulators packed along N (f32x2).
// A stored duplicated (a,a) in smem (broadcast reads); W in swizzled pair layout
// (conflict-free LDS.64). Double-buffered smem, one sync per k-slab.
__global__ __launch_bounds__(256,2) void gemm_f32(
    const float* __restrict__ A, const float* __restrict__ W,
    const float* __restrict__ bias, float* __restrict__ Y,
    int M, int Nout, int K, int act)
{
    __shared__ __align__(16) float As[2][8][256];   // (a,a) pairs along M
    __shared__ __align__(16) float Ws[2][8][128];   // swizzled: jp*32 + tx*2 + e
    const int tid = threadIdx.x;
    const int m0 = blockIdx.y * 128, n0 = blockIdx.x * 128;
    const int lrow = tid >> 1, lk = (tid & 1) * 4;
    const int ty = tid >> 4, tx = tid & 15;

    const float* Ap = A + (size_t)(m0 + lrow) * K + lk;
    const float* Wp = W + (size_t)(n0 + lrow) * K + lk;

    // swizzled W store index for column lrow
    const int wj = ((lrow & 6) >> 1) * 32 + (lrow >> 3) * 2 + (lrow & 1);

    unsigned long long acc[8][4];
    #pragma unroll
    for (int i = 0; i < 8; i++)
        #pragma unroll
        for (int j = 0; j < 4; j++) acc[i][j] = 0ull;

    const int kiter = K >> 3;
    float4 a4 = *(const float4*)Ap;
    float4 w4 = *(const float4*)Wp;

    // fill buffer 0
    *(float2*)&As[0][lk+0][2*lrow] = make_float2(a4.x, a4.x);
    *(float2*)&As[0][lk+1][2*lrow] = make_float2(a4.y, a4.y);
    *(float2*)&As[0][lk+2][2*lrow] = make_float2(a4.z, a4.z);
    *(float2*)&As[0][lk+3][2*lrow] = make_float2(a4.w, a4.w);
    Ws[0][lk+0][wj] = w4.x; Ws[0][lk+1][wj] = w4.y;
    Ws[0][lk+2][wj] = w4.z; Ws[0][lk+3][wj] = w4.w;
    __syncthreads();

    for (int kt = 0; kt < kiter; kt++) {
        const int cur = kt & 1, nxt = cur ^ 1;
        if (kt + 1 < kiter) {
            a4 = *(const float4*)(Ap + (kt + 1) * 8);
            w4 = *(const float4*)(Wp + (kt + 1) * 8);
        }
        #pragma unroll
        for (int kk = 0; kk < 8; kk++) {
            double2 A01 = *(const double2*)&As[cur][kk][16*ty];
            double2 A23 = *(const double2*)&As[cur][kk][16*ty + 4];
            double2 A45 = *(const double2*)&As[cur][kk][16*ty + 8];
            double2 A67 = *(const double2*)&As[cur][kk][16*ty + 12];
            double  W0  = *(const double*)&Ws[cur][kk][tx*2];
            double  W1  = *(const double*)&Ws[cur][kk][32 + tx*2];
            double  W2  = *(const double*)&Ws[cur][kk][64 + tx*2];
            double  W3  = *(const double*)&Ws[cur][kk][96 + tx*2];
            unsigned long long a[8] = { dl(A01.x), dl(A01.y), dl(A23.x), dl(A23.y),
                                        dl(A45.x), dl(A45.y), dl(A67.x), dl(A67.y) };
            unsigned long long w[4] = { dl(W0), dl(W1), dl(W2), dl(W3) };
            #pragma unroll
            for (int i = 0; i < 8; i++)
                #pragma unroll
                for (int jp = 0; jp < 4; jp++)
                    fma2(acc[i][jp], a[i], w[jp]);
        }
        if (kt + 1 < kiter) {
            *(float2*)&As[nxt][lk+0][2*lrow] = make_float2(a4.x, a4.x);
            *(float2*)&As[nxt][lk+1][2*lrow] = make_float2(a4.y, a4.y);
            *(float2*)&As[nxt][lk+2][2*lrow] = make_float2(a4.z, a4.z);
            *(float2*)&As[nxt][lk+3][2*lrow] = make_float2(a4.w, a4.w);
            Ws[nxt][lk+0][wj] = w4.x; Ws[nxt][lk+1][wj] = w4.y;
            Ws[nxt][lk+2][wj] = w4.z; Ws[nxt][lk+3][wj] = w4.w;
            __syncthreads();
        }
    }

    #pragma unroll
    for (int i = 0; i < 8; i++) {
        int row = m0 + ty*8 + i;
        float* yrow = Y + (size_t)row * Nout + n0 + tx*8;
        #pragma unroll
        for (int jp = 0; jp < 4; jp++) {
            float2 v  = u2f(acc[i][jp]);
            float2 bv = *(const float2*)&bias[n0 + tx*8 + 2*jp];
            float r0 = v.x + bv.x, r1 = v.y + bv.y;
            if (act == 1) { r0 = r0 * normcdff(r0); r1 = r1 * normcdff(r1); }
            *(float2*)&yrow[2*jp] = make_float2(r0, r1);
        }
    }
}

// ---------------- per-token normalize ----------------
__global__ void normalize_kernel(const float* __restrict__ qe,
                                 const float* __restrict__ temp,
                                 const float* __restrict__ sls)
{
    int bn = blockIdx.x;
    int n  = bn & (NTOK - 1);
    int c  = threadIdx.x;
    int h  = c >> 5;

    float yq = g_qraw [bn*CC + c];
    float yk = g_kvraw[(size_t)bn*2*CC + c];
    float yv = g_kvraw[(size_t)bn*2*CC + CC + c];

    float sq = yq*yq;
    #pragma unroll
    for (int o = 16; o; o >>= 1) sq += __shfl_xor_sync(0xffffffffu, sq, o);
    float qn = yq / fmaxf(sqrtf(sq), 1e-12f);

    float sk = yk*yk;
    #pragma unroll
    for (int o = 16; o; o >>= 1) sk += __shfl_xor_sync(0xffffffffu, sk, o);
    float kn = yk / fmaxf(sqrtf(sk), 1e-12f);

    float scale = log1pf(expf(temp[h])) * sls[n];

    g_qn[bn*CC + c] = qn;
    g_qs[bn*CC + c] = (qn + qe[c]) * scale;
    g_kn[bn*CC + c] = kn;
    g_v [bn*CC + c] = yv;
}

// ---------------- 8x8 avg pool + layernorm ----------------
__global__ void pool_ln_kernel(const float* __restrict__ ng,
                               const float* __restrict__ nb)
{
    int bp = blockIdx.x;               // b*64 + p
    int b  = bp >> 6, p = bp & 63;
    int ph = p >> 3, pw = p & 7;
    int c  = threadIdx.x;

    float s = 0.f;
    for (int r = 0; r < 8; r++)
        #pragma unroll
        for (int q = 0; q < 8; q++) {
            int n = (ph*8 + r) * 64 + pw*8 + q;
            s += g_xs[(size_t)(b*NTOK + n)*CC + c];
        }
    float avg = s * (1.f/64.f);

    float v1 = avg, v2 = avg*avg;
    #pragma unroll
    for (int o = 16; o; o >>= 1) {
        v1 += __shfl_xor_sync(0xffffffffu, v1, o);
        v2 += __shfl_xor_sync(0xffffffffu, v2, o);
    }
    __shared__ float s1[8], s2[8];
    int w = c >> 5, lane = c & 31;
    if (lane == 0) { s1[w] = v1; s2[w] = v2; }
    __syncthreads();
    float m1 = 0.f, m2 = 0.f;
    #pragma unroll
    for (int ww = 0; ww < 8; ww++) { m1 += s1[ww]; m2 += s2[ww]; }
    m1 *= (1.f/256.f); m2 *= (1.f/256.f);
    float var = m2 - m1*m1;
    g_pln[bp*CC + c] = (avg - m1) * rsqrtf(var + 1e-5f) * ng[c] + nb[c];
}

// ---------------- pooled kv projection + k_pool l2norm ----------------
__global__ void kvpool_kernel(const float* __restrict__ kv_w,
                              const float* __restrict__ kv_b)
{
    int bp = blockIdx.x; int b = bp >> 6, p = bp & 63;
    __shared__ __align__(16) float xr[CC];
    int tid = threadIdx.x;             // 0..511
    if (tid < CC) xr[tid] = g_pln[bp*CC + tid];
    __syncthreads();

    int o = tid;
    float acc = kv_b[o];
    const float4* w4 = (const float4*)(kv_w + (size_t)o * CC);
    const float4* x4 = (const float4*)xr;
    #pragma unroll 8
    for (int k = 0; k < 64; k++) {
        float4 w = w4[k], xv = x4[k];
        acc += w.x*xv.x + w.y*xv.y + w.z*xv.z + w.w*xv.w;
    }
    int lane = tid & 31;
    if (o < CC) {
        float s = acc*acc;
        #pragma unroll
        for (int q = 16; q; q >>= 1) s += __shfl_xor_sync(0xffffffffu, s, q);
        float kn = acc / fmaxf(sqrtf(s), 1e-12f);
        int h = o >> 5;
        g_kpT[((b*NHH + h)*HDD + lane)*PP + p] = kn;
    } else {
        int oo = o - CC; int h = oo >> 5, d = oo & 31;
        g_vpl[((b*NHH + h)*PP + p)*HDD + d] = acc;
    }
}

// ---------------- CPB MLP ----------------
__global__ void cpb_kernel(const float* __restrict__ table,
                           const float* __restrict__ w1, const float* __restrict__ b1,
                           const float* __restrict__ w2, const float* __restrict__ b2)
{
    __shared__ float sw1[1024], sb1[512], sw2[4096];
    int tid = threadIdx.x;             // 128
    for (int i = tid; i < 1024; i += 128) sw1[i] = w1[i];
    for (int i = tid; i <  512; i += 128) sb1[i] = b1[i];
    for (int i = tid; i < 4096; i += 128) sw2[i] = w2[i];
    __syncthreads();

    int t = blockIdx.x * 128 + tid;
    float c0 = table[2*t], c1 = table[2*t+1];
    float acc[NHH];
    #pragma unroll
    for (int h = 0; h < NHH; h++) acc[h] = b2[h];
    for (int j = 0; j < 512; j++) {
        float hj = fmaxf(fmaf(c0, sw1[2*j], fmaf(c1, sw1[2*j+1], sb1[j])), 0.f);
        #pragma unroll
        for (int h = 0; h < NHH; h++) acc[h] = fmaf(hj, sw2[h*512 + j], acc[h]);
    }
    #pragma unroll
    for (int h = 0; h < NHH; h++) g_cpb[t*NHH + h] = acc[h];
}

// ---------------- pool bias gather ----------------
__global__ void pbias_kernel(const int* __restrict__ rpi)
{
    int n = blockIdx.x, tid = threadIdx.x;     // 512 = h*64+p
    int h = tid >> 6, p = tid & 63;
    int r = rpi[n*PP + p];
    g_pb[(size_t)n*512 + tid] = g_cpb[r*NHH + h];
}

// ---------------- fused attention ----------------
#define SM_KPT 0
#define SM_VPL 16384
#define SM_LT  32768
#define SM_RPB 35072
#define SM_LB  35144
#define SM_QB  35216
#define SM_AP  35728
#define SM_TOT 36752

__global__ __launch_bounds__(512) void attn_kernel(
    const float* __restrict__ rpb_g, const float* __restrict__ lt_g,
    const float* __restrict__ lb_g)
{
    extern __shared__ __align__(16) float sm[];
    float* kpT  = sm + SM_KPT;
    float* vpl  = sm + SM_VPL;
    float* lt   = sm + SM_LT;
    float* rpb  = sm + SM_RPB;
    float* lb   = sm + SM_LB;
    float* qbuf = sm + SM_QB;
    float* apb  = sm + SM_AP;

    int tid = threadIdx.x;
    int b = blockIdx.y, chunk = blockIdx.x;

    for (int i = tid; i < 4096; i += 512) {
        ((float4*)kpT)[i] = ((const float4*)(g_kpT + (size_t)b*16384))[i];
        ((float4*)vpl)[i] = ((const float4*)(g_vpl + (size_t)b*16384))[i];
    }
    for (int i = tid; i < 2304; i += 512) lt[i] = lt_g[i];
    if (tid < 72) { rpb[tid] = rpb_g[tid]; lb[tid] = lb_g[tid]; }
    __syncthreads();

    int w = tid >> 5, lane = tid & 31;
    int h = w & 7, sub = w >> 3;
    const float* kh = kpT + h * (HDD*PP);
    const float* vh = vpl + h * (PP*HDD);

    float rpbl[LL], lbl[LL], ltv[LL];
    #pragma unroll
    for (int l = 0; l < LL; l++) {
        rpbl[l] = rpb[h*LL + l];
        lbl [l] = lb [h*LL + l];
        ltv [l] = lt [h*(HDD*LL) + lane*LL + l];
    }

    for (int t = 0; t < 64; t++) {
        int n = chunk*128 + 2*t + sub;
        int i = n >> 6, j = n & 63;
        size_t base = (size_t)(b*NTOK + n)*CC + h*HDD + lane;
        float qsc = g_qs[base];
        float qnv = g_qn[base];

        qbuf[w*32 + lane] = qsc;
        __syncwarp();

        float kvv[LL];
        #pragma unroll
        for (int l = 0; l < LL; l++) {
            int ii = i + l/3 - 1, jj = j + l%3 - 1;
            bool vl = ((unsigned)ii < 64u) && ((unsigned)jj < 64u);
            kvv[l] = vl ? g_kn[(size_t)(b*NTOK + ii*64 + jj)*CC + h*HDD + lane] : 0.f;
        }
        float el[LL], alt[LL];
        #pragma unroll
        for (int l = 0; l < LL; l++) {
            int ii = i + l/3 - 1, jj = j + l%3 - 1;
            bool vl = ((unsigned)ii < 64u) && ((unsigned)jj < 64u);
            float s = qsc * kvv[l];
            float a = qnv * ltv[l];
            #pragma unroll
            for (int o = 16; o; o >>= 1) {
                s += __shfl_xor_sync(0xffffffffu, s, o);
                a += __shfl_xor_sync(0xffffffffu, a, o);
            }
            el [l] = vl ? (s + rpbl[l]) : -1e30f;
            alt[l] = a + lbl[l];
        }

        float pl0 = 0.f, pl1 = 0.f;
        #pragma unroll
        for (int d = 0; d < 32; d++) {
            float qd = qbuf[w*32 + d];
            pl0 = fmaf(qd, kh[d*64 + lane],      pl0);
            pl1 = fmaf(qd, kh[d*64 + lane + 32], pl1);
        }
        pl0 += g_pb[(size_t)n*512 + h*64 + lane];
        pl1 += g_pb[(size_t)n*512 + h*64 + lane + 32];

        float m = fmaxf(pl0, pl1);
        #pragma unroll
        for (int l = 0; l < LL; l++) m = fmaxf(m, el[l]);
        #pragma unroll
        for (int o = 16; o; o >>= 1) m = fmaxf(m, __shfl_xor_sync(0xffffffffu, m, o));
        float ls = 0.f;
        #pragma unroll
        for (int l = 0; l < LL; l++) { el[l] = __expf(el[l] - m); ls += el[l]; }
        float e0 = __expf(pl0 - m), e1 = __expf(pl1 - m);
        float ps = e0 + e1;
        #pragma unroll
        for (int o = 16; o; o >>= 1) ps += __shfl_xor_sync(0xffffffffu, ps, o);
        float inv = 1.f / (ls + ps);

        float xo = 0.f;
        #pragma unroll
        for (int l = 0; l < LL; l++) {
            int ii = i + l/3 - 1, jj = j + l%3 - 1;
            if (((unsigned)ii < 64u) && ((unsigned)jj < 64u)) {
                float a = el[l]*inv + alt[l];
                xo = fmaf(a, g_v[(size_t)(b*NTOK + ii*64 + jj)*CC + h*HDD + lane], xo);
            }
        }

        apb[w*64 + lane]      = e0 * inv;
        apb[w*64 + 32 + lane] = e1 * inv;
        __syncwarp();
        #pragma unroll 8
        for (int p = 0; p < 64; p++)
            xo = fmaf(apb[w*64 + p], vh[p*32 + lane], xo);

        g_att[base] = xo;
        __syncwarp();
    }
}

// ---------------- launch ----------------
extern "C" void kernel_launch(void* const* d_in, const int* in_sizes, int n_in,
                              void* d_out, int out_size)
{
    const float* x      = (const float*)d_in[0];
    const int*   rpi    = (const int*)  d_in[1];
    const float* table  = (const float*)d_in[2];
    const float* q_w    = (const float*)d_in[3];
    const float* q_b    = (const float*)d_in[4];
    const float* kv_w   = (const float*)d_in[5];
    const float* kv_b   = (const float*)d_in[6];
    const float* temp   = (const float*)d_in[7];
    const float* qe     = (const float*)d_in[8];
    const float* proj_w = (const float*)d_in[9];
    const float* proj_b = (const float*)d_in[10];
    const float* sr_w   = (const float*)d_in[11];
    const float* sr_b   = (const float*)d_in[12];
    const float* norm_g = (const float*)d_in[13];
    const float* norm_b = (const float*)d_in[14];
    const float* cpb1_w = (const float*)d_in[15];
    const float* cpb1_b = (const float*)d_in[16];
    const float* cpb2_w = (const float*)d_in[17];
    const float* cpb2_b = (const float*)d_in[18];
    const float* rpb    = (const float*)d_in[19];
    const float* lt     = (const float*)d_in[20];
    const float* lb     = (const float*)d_in[21];
    const float* sls    = (const float*)d_in[22];
    float* out = (float*)d_out;

    void *p_qraw, *p_kvraw, *p_xs, *p_att;
    cudaGetSymbolAddress(&p_qraw,  g_qraw);
    cudaGetSymbolAddress(&p_kvraw, g_kvraw);
    cudaGetSymbolAddress(&p_xs,    g_xs);
    cudaGetSymbolAddress(&p_att,   g_att);

    const int M = BB * NTOK;

    // Launch order arranged so the ncu capture slot (observed = 4th launch)
    // lands on the kv GEMM (the biggest unknown).
    cpb_kernel<<<TT/128, 128>>>(table, cpb1_w, cpb1_b, cpb2_w, cpb2_b);
    pbias_kernel<<<NTOK, 512>>>(rpi);
    gemm_f32<<<dim3(2, M/128), 256>>>(x, sr_w, sr_b, (float*)p_xs,    M, CC,   CC, 1);
    gemm_f32<<<dim3(4, M/128), 256>>>(x, kv_w, kv_b, (float*)p_kvraw, M, 2*CC, CC, 0);
    gemm_f32<<<dim3(2, M/128), 256>>>(x, q_w,  q_b,  (float*)p_qraw,  M, CC,   CC, 0);

    normalize_kernel<<<M, CC>>>(qe, temp, sls);
    pool_ln_kernel<<<BB*PP, CC>>>(norm_g, norm_b);
    kvpool_kernel<<<BB*PP, 512>>>(kv_w, kv_b);

    cudaFuncSetAttribute(attn_kernel, cudaFuncAttributeMaxDynamicSharedMemorySize,
                         SM_TOT * sizeof(float));
    attn_kernel<<<dim3(32, BB), 512, SM_TOT * sizeof(float)>>>(rpb, lt, lb);

    gemm_f32<<<dim3(2, M/128), 256>>>((const float*)p_att, proj_w, proj_b, out, M, CC, CC, 0);
}

// round 6
// speedup vs baseline: 1.4701x; 1.4701x over previous
#include <cuda_runtime.h>
#include <cuda_bf16.h>
#include <cstdint>

#define BB   4
#define NTOK 4096
#define CC   256
#define NHH  8
#define HDD  32
#define LL   9
#define PP   64
#define TT   4096

// ---------------- scratch ----------------
__device__ float g_qraw [BB*NTOK*CC];
__device__ float g_kvraw[BB*NTOK*2*CC];
__device__ float g_qs   [BB*NTOK*CC];
__device__ float g_qn   [BB*NTOK*CC];
__device__ float g_kn   [BB*NTOK*CC];
__device__ float g_v    [BB*NTOK*CC];
__device__ float g_xs   [BB*NTOK*CC];
__device__ float g_pln  [BB*PP*CC];
__device__ float g_kpT  [BB*NHH*HDD*PP];
__device__ float g_vpl  [BB*NHH*PP*HDD];
__device__ float g_cpb  [TT*NHH];
__device__ float g_pb   [NTOK*NHH*PP];
__device__ float g_att  [BB*NTOK*CC];

// bf16 hi/lo split operands
__device__ __nv_bfloat16 g_xh [BB*NTOK*CC], g_xl [BB*NTOK*CC];
__device__ __nv_bfloat16 g_ath[BB*NTOK*CC], g_atl[BB*NTOK*CC];
__device__ __nv_bfloat16 g_qwh[CC*CC],      g_qwl[CC*CC];
__device__ __nv_bfloat16 g_kwh[2*CC*CC],    g_kwl[2*CC*CC];
__device__ __nv_bfloat16 g_swh[CC*CC],      g_swl[CC*CC];
__device__ __nv_bfloat16 g_pwh[CC*CC],      g_pwl[CC*CC];

// ---------------- helpers ----------------
__device__ __forceinline__ uint32_t smem_u32(const void* p) {
    uint32_t a;
    asm("{ .reg .u64 t; cvta.to.shared.u64 t, %1; cvt.u32.u64 %0, t; }" : "=r"(a) : "l"(p));
    return a;
}
__device__ __forceinline__ void cp_async16(uint32_t dst, const void* src) {
    asm volatile("cp.async.cg.shared.global [%0], [%1], 16;" :: "r"(dst), "l"(src) : "memory");
}
#define CP_COMMIT() asm volatile("cp.async.commit_group;" ::: "memory")
#define CP_WAIT0()  asm volatile("cp.async.wait_group 0;" ::: "memory")

__device__ __forceinline__ void ldmx4(uint32_t* r, uint32_t addr) {
    asm volatile("ldmatrix.sync.aligned.m8n8.x4.shared.b16 {%0,%1,%2,%3}, [%4];"
                 : "=r"(r[0]), "=r"(r[1]), "=r"(r[2]), "=r"(r[3]) : "r"(addr));
}
__device__ __forceinline__ void mma16816(float* c, const uint32_t* a, uint32_t b0, uint32_t b1) {
    asm volatile("mma.sync.aligned.m16n8k16.row.col.f32.bf16.bf16.f32 "
                 "{%0,%1,%2,%3}, {%4,%5,%6,%7}, {%8,%9}, {%0,%1,%2,%3};"
                 : "+f"(c[0]), "+f"(c[1]), "+f"(c[2]), "+f"(c[3])
                 : "r"(a[0]), "r"(a[1]), "r"(a[2]), "r"(a[3]), "r"(b0), "r"(b1));
}

// ---------------- hi/lo split conversion ----------------
__global__ void cvt_hilo(const float* __restrict__ src,
                         __nv_bfloat16* __restrict__ hi,
                         __nv_bfloat16* __restrict__ lo, int n)
{
    int i = blockIdx.x * 256 + threadIdx.x;
    if (i < n) {
        float v = src[i];
        __nv_bfloat16 h = __float2bfloat16(v);
        hi[i] = h;
        lo[i] = __float2bfloat16(v - __bfloat162float(h));
    }
}

// ---------------- HMMA GEMM: Y[m,o] = A[m,:]·W[o,:] + bias[o] ----------------
// Virtual K'=768 over 12 chunks of 64: segments [Ah·Wh | Ah·Wl | Al·Wh].
// Tile 128x128, 8 warps (2M x 4N), mma.m16n8k16 bf16, cp.async double buffer.
#define GS_A0   0
#define GS_A1   16384
#define GS_W0   32768
#define GS_W1   49152
#define GS_BIAS 65536
#define GS_TOT  66048

__global__ __launch_bounds__(256) void gemm_mma(
    const __nv_bfloat16* __restrict__ Ah, const __nv_bfloat16* __restrict__ Al,
    const __nv_bfloat16* __restrict__ Wh, const __nv_bfloat16* __restrict__ Wl,
    const float* __restrict__ bias, float* __restrict__ Y, int Nout, int act)
{
    extern __shared__ __align__(128) char smem[];
    const uint32_t sb = smem_u32(smem);
    float* sbias = (float*)(smem + GS_BIAS);

    const int tid = threadIdx.x, wid = tid >> 5, lane = tid & 31;
    const int n0 = blockIdx.x * 128, m0 = blockIdx.y * 128;
    const int warp_m = wid & 1, warp_n = wid >> 1;

    if (tid < 128) sbias[tid] = bias[n0 + tid];

    float acc[4][4][4];
    #pragma unroll
    for (int i = 0; i < 4; i++)
        #pragma unroll
        for (int j = 0; j < 4; j++)
            #pragma unroll
            for (int e = 0; e < 4; e++) acc[i][j][e] = 0.f;

    // per-thread load geometry (4 uint4 per operand per chunk)
    const int lrow0 = tid >> 3;             // +32 per i
    const int luc   = tid & 7;

    auto issue = [&](int c, int buf) {
        int seg = c >> 2, ks0 = (c & 3) * 64;
        const __nv_bfloat16* Asrc = (seg < 2) ? Ah : Al;
        const __nv_bfloat16* Wsrc = (seg == 1) ? Wl : Wh;
        uint32_t ab = sb + (buf ? GS_A1 : GS_A0);
        uint32_t wb = sb + (buf ? GS_W1 : GS_W0);
        #pragma unroll
        for (int i = 0; i < 4; i++) {
            int row = lrow0 + i * 32;
            uint32_t soff = (uint32_t)row * 128 + (uint32_t)((luc ^ (row & 7)) * 16);
            cp_async16(ab + soff, Asrc + (size_t)(m0 + row) * CC + ks0 + luc * 8);
            cp_async16(wb + soff, Wsrc + (size_t)(n0 + row) * CC + ks0 + luc * 8);
        }
        CP_COMMIT();
    };

    issue(0, 0);

    for (int c = 0; c < 12; c++) {
        CP_WAIT0();
        __syncthreads();
        if (c + 1 < 12) issue(c + 1, (c + 1) & 1);

        const uint32_t ab = sb + ((c & 1) ? GS_A1 : GS_A0);
        const uint32_t wb = sb + ((c & 1) ? GS_W1 : GS_W0);

        #pragma unroll
        for (int ks = 0; ks < 4; ks++) {
            uint32_t afr[4][4];
            #pragma unroll
            for (int tm = 0; tm < 4; tm++) {
                int row = warp_m * 64 + tm * 16 + (lane & 15);
                int cc  = ks * 2 + (lane >> 4);
                ldmx4(afr[tm], ab + (uint32_t)row * 128 + (uint32_t)((cc ^ (row & 7)) * 16));
            }
            uint32_t bfr[2][4];
            #pragma unroll
            for (int tp = 0; tp < 2; tp++) {
                int g = lane >> 3;
                int row = warp_n * 32 + tp * 16 + ((g >> 1) & 1) * 8 + (lane & 7);
                int cc  = ks * 2 + (g & 1);
                ldmx4(bfr[tp], wb + (uint32_t)row * 128 + (uint32_t)((cc ^ (row & 7)) * 16));
            }
            #pragma unroll
            for (int tm = 0; tm < 4; tm++)
                #pragma unroll
                for (int tn = 0; tn < 4; tn++)
                    mma16816(acc[tm][tn], afr[tm],
                             bfr[tn >> 1][(tn & 1) * 2], bfr[tn >> 1][(tn & 1) * 2 + 1]);
        }
    }

    // epilogue: direct fragment stores
    #pragma unroll
    for (int tm = 0; tm < 4; tm++) {
        int gr = m0 + warp_m * 64 + tm * 16 + (lane >> 2);
        #pragma unroll
        for (int tn = 0; tn < 4; tn++) {
            int lc = warp_n * 32 + tn * 8 + 2 * (lane & 3);
            int gc = n0 + lc;
            float b0 = sbias[lc], b1 = sbias[lc + 1];
            float r0 = acc[tm][tn][0] + b0, r1 = acc[tm][tn][1] + b1;
            float r2 = acc[tm][tn][2] + b0, r3 = acc[tm][tn][3] + b1;
            if (act == 1) {
                r0 *= normcdff(r0); r1 *= normcdff(r1);
                r2 *= normcdff(r2); r3 *= normcdff(r3);
            }
            *(float2*)&Y[(size_t)gr * Nout + gc]       = make_float2(r0, r1);
            *(float2*)&Y[(size_t)(gr + 8) * Nout + gc] = make_float2(r2, r3);
        }
    }
}

// ---------------- per-token normalize ----------------
__global__ void normalize_kernel(const float* __restrict__ qe,
                                 const float* __restrict__ temp,
                                 const float* __restrict__ sls)
{
    int bn = blockIdx.x;
    int n  = bn & (NTOK - 1);
    int c  = threadIdx.x;
    int h  = c >> 5;

    float yq = g_qraw [bn*CC + c];
    float yk = g_kvraw[(size_t)bn*2*CC + c];
    float yv = g_kvraw[(size_t)bn*2*CC + CC + c];

    float sq = yq*yq;
    #pragma unroll
    for (int o = 16; o; o >>= 1) sq += __shfl_xor_sync(0xffffffffu, sq, o);
    float qn = yq / fmaxf(sqrtf(sq), 1e-12f);

    float sk = yk*yk;
    #pragma unroll
    for (int o = 16; o; o >>= 1) sk += __shfl_xor_sync(0xffffffffu, sk, o);
    float kn = yk / fmaxf(sqrtf(sk), 1e-12f);

    float scale = log1pf(expf(temp[h])) * sls[n];

    g_qn[bn*CC + c] = qn;
    g_qs[bn*CC + c] = (qn + qe[c]) * scale;
    g_kn[bn*CC + c] = kn;
    g_v [bn*CC + c] = yv;
}

// ---------------- 8x8 avg pool + layernorm ----------------
__global__ void pool_ln_kernel(const float* __restrict__ ng,
                               const float* __restrict__ nb)
{
    int bp = blockIdx.x;
    int b  = bp >> 6, p = bp & 63;
    int ph = p >> 3, pw = p & 7;
    int c  = threadIdx.x;

    float s = 0.f;
    for (int r = 0; r < 8; r++)
        #pragma unroll
        for (int q = 0; q < 8; q++) {
            int n = (ph*8 + r) * 64 + pw*8 + q;
            s += g_xs[(size_t)(b*NTOK + n)*CC + c];
        }
    float avg = s * (1.f/64.f);

    float v1 = avg, v2 = avg*avg;
    #pragma unroll
    for (int o = 16; o; o >>= 1) {
        v1 += __shfl_xor_sync(0xffffffffu, v1, o);
        v2 += __shfl_xor_sync(0xffffffffu, v2, o);
    }
    __shared__ float s1[8], s2[8];
    int w = c >> 5, lane = c & 31;
    if (lane == 0) { s1[w] = v1; s2[w] = v2; }
    __syncthreads();
    float m1 = 0.f, m2 = 0.f;
    #pragma unroll
    for (int ww = 0; ww < 8; ww++) { m1 += s1[ww]; m2 += s2[ww]; }
    m1 *= (1.f/256.f); m2 *= (1.f/256.f);
    float var = m2 - m1*m1;
    g_pln[bp*CC + c] = (avg - m1) * rsqrtf(var + 1e-5f) * ng[c] + nb[c];
}

// ---------------- pooled kv projection + k_pool l2norm ----------------
__global__ void kvpool_kernel(const float* __restrict__ kv_w,
                              const float* __restrict__ kv_b)
{
    int bp = blockIdx.x; int b = bp >> 6, p = bp & 63;
    __shared__ __align__(16) float xr[CC];
    int tid = threadIdx.x;
    if (tid < CC) xr[tid] = g_pln[bp*CC + tid];
    __syncthreads();

    int o = tid;
    float acc = kv_b[o];
    const float4* w4 = (const float4*)(kv_w + (size_t)o * CC);
    const float4* x4 = (const float4*)xr;
    #pragma unroll 8
    for (int k = 0; k < 64; k++) {
        float4 w = w4[k], xv = x4[k];
        acc += w.x*xv.x + w.y*xv.y + w.z*xv.z + w.w*xv.w;
    }
    int lane = tid & 31;
    if (o < CC) {
        float s = acc*acc;
        #pragma unroll
        for (int q = 16; q; q >>= 1) s += __shfl_xor_sync(0xffffffffu, s, q);
        float kn = acc / fmaxf(sqrtf(s), 1e-12f);
        int h = o >> 5;
        g_kpT[((b*NHH + h)*HDD + lane)*PP + p] = kn;
    } else {
        int oo = o - CC; int h = oo >> 5, d = oo & 31;
        g_vpl[((b*NHH + h)*PP + p)*HDD + d] = acc;
    }
}

// ---------------- CPB MLP ----------------
__global__ void cpb_kernel(const float* __restrict__ table,
                           const float* __restrict__ w1, const float* __restrict__ b1,
                           const float* __restrict__ w2, const float* __restrict__ b2)
{
    __shared__ float sw1[1024], sb1[512], sw2[4096];
    int tid = threadIdx.x;
    for (int i = tid; i < 1024; i += 128) sw1[i] = w1[i];
    for (int i = tid; i <  512; i += 128) sb1[i] = b1[i];
    for (int i = tid; i < 4096; i += 128) sw2[i] = w2[i];
    __syncthreads();

    int t = blockIdx.x * 128 + tid;
    float c0 = table[2*t], c1 = table[2*t+1];
    float acc[NHH];
    #pragma unroll
    for (int h = 0; h < NHH; h++) acc[h] = b2[h];
    for (int j = 0; j < 512; j++) {
        float hj = fmaxf(fmaf(c0, sw1[2*j], fmaf(c1, sw1[2*j+1], sb1[j])), 0.f);
        #pragma unroll
        for (int h = 0; h < NHH; h++) acc[h] = fmaf(hj, sw2[h*512 + j], acc[h]);
    }
    #pragma unroll
    for (int h = 0; h < NHH; h++) g_cpb[t*NHH + h] = acc[h];
}

// ---------------- pool bias gather ----------------
__global__ void pbias_kernel(const int* __restrict__ rpi)
{
    int n = blockIdx.x, tid = threadIdx.x;
    int h = tid >> 6, p = tid & 63;
    int r = rpi[n*PP + p];
    g_pb[(size_t)n*512 + tid] = g_cpb[r*NHH + h];
}

// ---------------- fused attention ----------------
#define SM_KPT 0
#define SM_VPL 16384
#define SM_LT  32768
#define SM_RPB 35072
#define SM_LB  35144
#define SM_QB  35216
#define SM_AP  35728
#define SM_TOT 36752

__global__ __launch_bounds__(512) void attn_kernel(
    const float* __restrict__ rpb_g, const float* __restrict__ lt_g,
    const float* __restrict__ lb_g)
{
    extern __shared__ __align__(16) float sm[];
    float* kpT  = sm + SM_KPT;
    float* vpl  = sm + SM_VPL;
    float* lt   = sm + SM_LT;
    float* rpb  = sm + SM_RPB;
    float* lb   = sm + SM_LB;
    float* qbuf = sm + SM_QB;
    float* apb  = sm + SM_AP;

    int tid = threadIdx.x;
    int b = blockIdx.y, chunk = blockIdx.x;

    for (int i = tid; i < 4096; i += 512) {
        ((float4*)kpT)[i] = ((const float4*)(g_kpT + (size_t)b*16384))[i];
        ((float4*)vpl)[i] = ((const float4*)(g_vpl + (size_t)b*16384))[i];
    }
    for (int i = tid; i < 2304; i += 512) lt[i] = lt_g[i];
    if (tid < 72) { rpb[tid] = rpb_g[tid]; lb[tid] = lb_g[tid]; }
    __syncthreads();

    int w = tid >> 5, lane = tid & 31;
    int h = w & 7, sub = w >> 3;
    const float* kh = kpT + h * (HDD*PP);
    const float* vh = vpl + h * (PP*HDD);

    float rpbl[LL], lbl[LL], ltv[LL];
    #pragma unroll
    for (int l = 0; l < LL; l++) {
        rpbl[l] = rpb[h*LL + l];
        lbl [l] = lb [h*LL + l];
        ltv [l] = lt [h*(HDD*LL) + lane*LL + l];
    }

    for (int t = 0; t < 64; t++) {
        int n = chunk*128 + 2*t + sub;
        int i = n >> 6, j = n & 63;
        size_t base = (size_t)(b*NTOK + n)*CC + h*HDD + lane;
        float qsc = g_qs[base];
        float qnv = g_qn[base];

        qbuf[w*32 + lane] = qsc;
        __syncwarp();

        float kvv[LL];
        #pragma unroll
        for (int l = 0; l < LL; l++) {
            int ii = i + l/3 - 1, jj = j + l%3 - 1;
            bool vl = ((unsigned)ii < 64u) && ((unsigned)jj < 64u);
            kvv[l] = vl ? g_kn[(size_t)(b*NTOK + ii*64 + jj)*CC + h*HDD + lane] : 0.f;
        }
        float el[LL], alt[LL];
        #pragma unroll
        for (int l = 0; l < LL; l++) {
            int ii = i + l/3 - 1, jj = j + l%3 - 1;
            bool vl = ((unsigned)ii < 64u) && ((unsigned)jj < 64u);
            float s = qsc * kvv[l];
            float a = qnv * ltv[l];
            #pragma unroll
            for (int o = 16; o; o >>= 1) {
                s += __shfl_xor_sync(0xffffffffu, s, o);
                a += __shfl_xor_sync(0xffffffffu, a, o);
            }
            el [l] = vl ? (s + rpbl[l]) : -1e30f;
            alt[l] = a + lbl[l];
        }

        float pl0 = 0.f, pl1 = 0.f;
        #pragma unroll
        for (int d = 0; d < 32; d++) {
            float qd = qbuf[w*32 + d];
            pl0 = fmaf(qd, kh[d*64 + lane],      pl0);
            pl1 = fmaf(qd, kh[d*64 + lane + 32], pl1);
        }
        pl0 += g_pb[(size_t)n*512 + h*64 + lane];
        pl1 += g_pb[(size_t)n*512 + h*64 + lane + 32];

        float m = fmaxf(pl0, pl1);
        #pragma unroll
        for (int l = 0; l < LL; l++) m = fmaxf(m, el[l]);
        #pragma unroll
        for (int o = 16; o; o >>= 1) m = fmaxf(m, __shfl_xor_sync(0xffffffffu, m, o));
        float ls = 0.f;
        #pragma unroll
        for (int l = 0; l < LL; l++) { el[l] = __expf(el[l] - m); ls += el[l]; }
        float e0 = __expf(pl0 - m), e1 = __expf(pl1 - m);
        float ps = e0 + e1;
        #pragma unroll
        for (int o = 16; o; o >>= 1) ps += __shfl_xor_sync(0xffffffffu, ps, o);
        float inv = 1.f / (ls + ps);

        float xo = 0.f;
        #pragma unroll
        for (int l = 0; l < LL; l++) {
            int ii = i + l/3 - 1, jj = j + l%3 - 1;
            if (((unsigned)ii < 64u) && ((unsigned)jj < 64u)) {
                float a = el[l]*inv + alt[l];
                xo = fmaf(a, g_v[(size_t)(b*NTOK + ii*64 + jj)*CC + h*HDD + lane], xo);
            }
        }

        apb[w*64 + lane]      = e0 * inv;
        apb[w*64 + 32 + lane] = e1 * inv;
        __syncwarp();
        #pragma unroll 8
        for (int p = 0; p < 64; p++)
            xo = fmaf(apb[w*64 + p], vh[p*32 + lane], xo);

        g_att[base] = xo;
        __syncwarp();
    }
}

// ---------------- launch ----------------
extern "C" void kernel_launch(void* const* d_in, const int* in_sizes, int n_in,
                              void* d_out, int out_size)
{
    const float* x      = (const float*)d_in[0];
    const int*   rpi    = (const int*)  d_in[1];
    const float* table  = (const float*)d_in[2];
    const float* q_w    = (const float*)d_in[3];
    const float* q_b    = (const float*)d_in[4];
    const float* kv_w   = (const float*)d_in[5];
    const float* kv_b   = (const float*)d_in[6];
    const float* temp   = (const float*)d_in[7];
    const float* qe     = (const float*)d_in[8];
    const float* proj_w = (const float*)d_in[9];
    const float* proj_b = (const float*)d_in[10];
    const float* sr_w   = (const float*)d_in[11];
    const float* sr_b   = (const float*)d_in[12];
    const float* norm_g = (const float*)d_in[13];
    const float* norm_b = (const float*)d_in[14];
    const float* cpb1_w = (const float*)d_in[15];
    const float* cpb1_b = (const float*)d_in[16];
    const float* cpb2_w = (const float*)d_in[17];
    const float* cpb2_b = (const float*)d_in[18];
    const float* rpb    = (const float*)d_in[19];
    const float* lt     = (const float*)d_in[20];
    const float* lb     = (const float*)d_in[21];
    const float* sls    = (const float*)d_in[22];
    float* out = (float*)d_out;

    void *p_qraw, *p_kvraw, *p_xs, *p_att;
    void *p_xh, *p_xl, *p_ath, *p_atl;
    void *p_qwh, *p_qwl, *p_kwh, *p_kwl, *p_swh, *p_swl, *p_pwh, *p_pwl;
    cudaGetSymbolAddress(&p_qraw,  g_qraw);
    cudaGetSymbolAddress(&p_kvraw, g_kvraw);
    cudaGetSymbolAddress(&p_xs,    g_xs);
    cudaGetSymbolAddress(&p_att,   g_att);
    cudaGetSymbolAddress(&p_xh,  g_xh);  cudaGetSymbolAddress(&p_xl,  g_xl);
    cudaGetSymbolAddress(&p_ath, g_ath); cudaGetSymbolAddress(&p_atl, g_atl);
    cudaGetSymbolAddress(&p_qwh, g_qwh); cudaGetSymbolAddress(&p_qwl, g_qwl);
    cudaGetSymbolAddress(&p_kwh, g_kwh); cudaGetSymbolAddress(&p_kwl, g_kwl);
    cudaGetSymbolAddress(&p_swh, g_swh); cudaGetSymbolAddress(&p_swl, g_swl);
    cudaGetSymbolAddress(&p_pwh, g_pwh); cudaGetSymbolAddress(&p_pwl, g_pwl);

    const int M = BB * NTOK;
    const int NX = M * CC;

    cudaFuncSetAttribute(gemm_mma, cudaFuncAttributeMaxDynamicSharedMemorySize, GS_TOT);
    cudaFuncSetAttribute(attn_kernel, cudaFuncAttributeMaxDynamicSharedMemorySize,
                         SM_TOT * sizeof(float));

    #define BF(p) ((__nv_bfloat16*)(p))
    // 1-3: conversions; 4: kv GEMM lands in the ncu capture slot
    cvt_hilo<<<(NX+255)/256, 256>>>(x, BF(p_xh), BF(p_xl), NX);
    cvt_hilo<<<(CC*CC+255)/256, 256>>>(q_w,  BF(p_qwh), BF(p_qwl), CC*CC);
    cvt_hilo<<<(2*CC*CC+255)/256, 256>>>(kv_w, BF(p_kwh), BF(p_kwl), 2*CC*CC);
    gemm_mma<<<dim3(4, M/128), 256, GS_TOT>>>(BF(p_xh), BF(p_xl), BF(p_kwh), BF(p_kwl),
                                              kv_b, (float*)p_kvraw, 2*CC, 0);
    cvt_hilo<<<(CC*CC+255)/256, 256>>>(sr_w,   BF(p_swh), BF(p_swl), CC*CC);
    cvt_hilo<<<(CC*CC+255)/256, 256>>>(proj_w, BF(p_pwh), BF(p_pwl), CC*CC);
    gemm_mma<<<dim3(2, M/128), 256, GS_TOT>>>(BF(p_xh), BF(p_xl), BF(p_qwh), BF(p_qwl),
                                              q_b, (float*)p_qraw, CC, 0);
    gemm_mma<<<dim3(2, M/128), 256, GS_TOT>>>(BF(p_xh), BF(p_xl), BF(p_swh), BF(p_swl),
                                              sr_b, (float*)p_xs, CC, 1);

    normalize_kernel<<<M, CC>>>(qe, temp, sls);
    pool_ln_kernel<<<BB*PP, CC>>>(norm_g, norm_b);
    kvpool_kernel<<<BB*PP, 512>>>(kv_w, kv_b);
    cpb_kernel<<<TT/128, 128>>>(table, cpb1_w, cpb1_b, cpb2_w, cpb2_b);
    pbias_kernel<<<NTOK, 512>>>(rpi);

    attn_kernel<<<dim3(32, BB), 512, SM_TOT * sizeof(float)>>>(rpb, lt, lb);

    cvt_hilo<<<(NX+255)/256, 256>>>((const float*)p_att, BF(p_ath), BF(p_atl), NX);
    gemm_mma<<<dim3(2, M/128), 256, GS_TOT>>>(BF(p_ath), BF(p_atl), BF(p_pwh), BF(p_pwl),
                                              proj_b, out, CC, 0);
    #undef BF
}

// round 7
// speedup vs baseline: 1.5828x; 1.0766x over previous
#include <cuda_runtime.h>
#include <cuda_bf16.h>
#include <cstdint>

#define BB   4
#define NTOK 4096
#define CC   256
#define NHH  8
#define HDD  32
#define LL   9
#define PP   64
#define TT   4096

// ---------------- scratch ----------------
__device__ float g_qraw [BB*NTOK*CC];
__device__ float g_kvraw[BB*NTOK*2*CC];
__device__ float g_qs   [BB*NTOK*CC];
__device__ float g_qn   [BB*NTOK*CC];
__device__ float g_kn   [BB*NTOK*CC];
__device__ float g_v    [BB*NTOK*CC];
__device__ float g_xs   [BB*NTOK*CC];
__device__ float g_pln  [BB*PP*CC];
__device__ float g_kpT  [BB*NHH*HDD*PP];   // [b][h][d][p]
__device__ float g_vpl  [BB*NHH*PP*HDD];   // [b][h][p][d]
__device__ float g_cpb  [TT*NHH];
__device__ float g_pb   [NTOK*NHH*PP];     // [n][h][p]

// bf16 hi/lo split operands
__device__ __nv_bfloat16 g_xh [BB*NTOK*CC], g_xl [BB*NTOK*CC];
__device__ __nv_bfloat16 g_ath[BB*NTOK*CC], g_atl[BB*NTOK*CC];
__device__ __nv_bfloat16 g_qwh[CC*CC],      g_qwl[CC*CC];
__device__ __nv_bfloat16 g_kwh[2*CC*CC],    g_kwl[2*CC*CC];
__device__ __nv_bfloat16 g_swh[CC*CC],      g_swl[CC*CC];
__device__ __nv_bfloat16 g_pwh[CC*CC],      g_pwl[CC*CC];

// ---------------- helpers ----------------
__device__ __forceinline__ uint32_t smem_u32(const void* p) {
    uint32_t a;
    asm("{ .reg .u64 t; cvta.to.shared.u64 t, %1; cvt.u32.u64 %0, t; }" : "=r"(a) : "l"(p));
    return a;
}
__device__ __forceinline__ void cp_async16(uint32_t dst, const void* src) {
    asm volatile("cp.async.cg.shared.global [%0], [%1], 16;" :: "r"(dst), "l"(src) : "memory");
}
#define CP_COMMIT() asm volatile("cp.async.commit_group;" ::: "memory")
#define CP_WAIT0()  asm volatile("cp.async.wait_group 0;" ::: "memory")

__device__ __forceinline__ void ldmx4(uint32_t* r, uint32_t addr) {
    asm volatile("ldmatrix.sync.aligned.m8n8.x4.shared.b16 {%0,%1,%2,%3}, [%4];"
                 : "=r"(r[0]), "=r"(r[1]), "=r"(r[2]), "=r"(r[3]) : "r"(addr));
}
__device__ __forceinline__ void mma16816(float* c, const uint32_t* a, uint32_t b0, uint32_t b1) {
    asm volatile("mma.sync.aligned.m16n8k16.row.col.f32.bf16.bf16.f32 "
                 "{%0,%1,%2,%3}, {%4,%5,%6,%7}, {%8,%9}, {%0,%1,%2,%3};"
                 : "+f"(c[0]), "+f"(c[1]), "+f"(c[2]), "+f"(c[3])
                 : "r"(a[0]), "r"(a[1]), "r"(a[2]), "r"(a[3]), "r"(b0), "r"(b1));
}

// ---------------- hi/lo split conversion ----------------
__global__ void cvt_hilo(const float* __restrict__ src,
                         __nv_bfloat16* __restrict__ hi,
                         __nv_bfloat16* __restrict__ lo, int n)
{
    int i = blockIdx.x * 256 + threadIdx.x;
    if (i < n) {
        float v = src[i];
        __nv_bfloat16 h = __float2bfloat16(v);
        hi[i] = h;
        lo[i] = __float2bfloat16(v - __bfloat162float(h));
    }
}

// ---------------- HMMA GEMM (unchanged from R6) ----------------
#define GS_A0   0
#define GS_A1   16384
#define GS_W0   32768
#define GS_W1   49152
#define GS_BIAS 65536
#define GS_TOT  66048

__global__ __launch_bounds__(256) void gemm_mma(
    const __nv_bfloat16* __restrict__ Ah, const __nv_bfloat16* __restrict__ Al,
    const __nv_bfloat16* __restrict__ Wh, const __nv_bfloat16* __restrict__ Wl,
    const float* __restrict__ bias, float* __restrict__ Y, int Nout, int act)
{
    extern __shared__ __align__(128) char smem[];
    const uint32_t sb = smem_u32(smem);
    float* sbias = (float*)(smem + GS_BIAS);

    const int tid = threadIdx.x, wid = tid >> 5, lane = tid & 31;
    const int n0 = blockIdx.x * 128, m0 = blockIdx.y * 128;
    const int warp_m = wid & 1, warp_n = wid >> 1;

    if (tid < 128) sbias[tid] = bias[n0 + tid];

    float acc[4][4][4];
    #pragma unroll
    for (int i = 0; i < 4; i++)
        #pragma unroll
        for (int j = 0; j < 4; j++)
            #pragma unroll
            for (int e = 0; e < 4; e++) acc[i][j][e] = 0.f;

    const int lrow0 = tid >> 3;
    const int luc   = tid & 7;

    auto issue = [&](int c, int buf) {
        int seg = c >> 2, ks0 = (c & 3) * 64;
        const __nv_bfloat16* Asrc = (seg < 2) ? Ah : Al;
        const __nv_bfloat16* Wsrc = (seg == 1) ? Wl : Wh;
        uint32_t ab = sb + (buf ? GS_A1 : GS_A0);
        uint32_t wb = sb + (buf ? GS_W1 : GS_W0);
        #pragma unroll
        for (int i = 0; i < 4; i++) {
            int row = lrow0 + i * 32;
            uint32_t soff = (uint32_t)row * 128 + (uint32_t)((luc ^ (row & 7)) * 16);
            cp_async16(ab + soff, Asrc + (size_t)(m0 + row) * CC + ks0 + luc * 8);
            cp_async16(wb + soff, Wsrc + (size_t)(n0 + row) * CC + ks0 + luc * 8);
        }
        CP_COMMIT();
    };

    issue(0, 0);

    for (int c = 0; c < 12; c++) {
        CP_WAIT0();
        __syncthreads();
        if (c + 1 < 12) issue(c + 1, (c + 1) & 1);

        const uint32_t ab = sb + ((c & 1) ? GS_A1 : GS_A0);
        const uint32_t wb = sb + ((c & 1) ? GS_W1 : GS_W0);

        #pragma unroll
        for (int ks = 0; ks < 4; ks++) {
            uint32_t afr[4][4];
            #pragma unroll
            for (int tm = 0; tm < 4; tm++) {
                int row = warp_m * 64 + tm * 16 + (lane & 15);
                int cc  = ks * 2 + (lane >> 4);
                ldmx4(afr[tm], ab + (uint32_t)row * 128 + (uint32_t)((cc ^ (row & 7)) * 16));
            }
            uint32_t bfr[2][4];
            #pragma unroll
            for (int tp = 0; tp < 2; tp++) {
                int g = lane >> 3;
                int row = warp_n * 32 + tp * 16 + ((g >> 1) & 1) * 8 + (lane & 7);
                int cc  = ks * 2 + (g & 1);
                ldmx4(bfr[tp], wb + (uint32_t)row * 128 + (uint32_t)((cc ^ (row & 7)) * 16));
            }
            #pragma unroll
            for (int tm = 0; tm < 4; tm++)
                #pragma unroll
                for (int tn = 0; tn < 4; tn++)
                    mma16816(acc[tm][tn], afr[tm],
                             bfr[tn >> 1][(tn & 1) * 2], bfr[tn >> 1][(tn & 1) * 2 + 1]);
        }
    }

    #pragma unroll
    for (int tm = 0; tm < 4; tm++) {
        int gr = m0 + warp_m * 64 + tm * 16 + (lane >> 2);
        #pragma unroll
        for (int tn = 0; tn < 4; tn++) {
            int lc = warp_n * 32 + tn * 8 + 2 * (lane & 3);
            int gc = n0 + lc;
            float b0 = sbias[lc], b1 = sbias[lc + 1];
            float r0 = acc[tm][tn][0] + b0, r1 = acc[tm][tn][1] + b1;
            float r2 = acc[tm][tn][2] + b0, r3 = acc[tm][tn][3] + b1;
            if (act == 1) {
                r0 *= normcdff(r0); r1 *= normcdff(r1);
                r2 *= normcdff(r2); r3 *= normcdff(r3);
            }
            *(float2*)&Y[(size_t)gr * Nout + gc]       = make_float2(r0, r1);
            *(float2*)&Y[(size_t)(gr + 8) * Nout + gc] = make_float2(r2, r3);
        }
    }
}

// ---------------- per-token normalize ----------------
__global__ void normalize_kernel(const float* __restrict__ qe,
                                 const float* __restrict__ temp,
                                 const float* __restrict__ sls)
{
    int bn = blockIdx.x;
    int n  = bn & (NTOK - 1);
    int c  = threadIdx.x;
    int h  = c >> 5;

    float yq = g_qraw [bn*CC + c];
    float yk = g_kvraw[(size_t)bn*2*CC + c];
    float yv = g_kvraw[(size_t)bn*2*CC + CC + c];

    float sq = yq*yq;
    #pragma unroll
    for (int o = 16; o; o >>= 1) sq += __shfl_xor_sync(0xffffffffu, sq, o);
    float qn = yq / fmaxf(sqrtf(sq), 1e-12f);

    float sk = yk*yk;
    #pragma unroll
    for (int o = 16; o; o >>= 1) sk += __shfl_xor_sync(0xffffffffu, sk, o);
    float kn = yk / fmaxf(sqrtf(sk), 1e-12f);

    float scale = log1pf(expf(temp[h])) * sls[n];

    g_qn[bn*CC + c] = qn;
    g_qs[bn*CC + c] = (qn + qe[c]) * scale;
    g_kn[bn*CC + c] = kn;
    g_v [bn*CC + c] = yv;
}

// ---------------- 8x8 avg pool + layernorm ----------------
__global__ void pool_ln_kernel(const float* __restrict__ ng,
                               const float* __restrict__ nb)
{
    int bp = blockIdx.x;
    int b  = bp >> 6, p = bp & 63;
    int ph = p >> 3, pw = p & 7;
    int c  = threadIdx.x;

    float s = 0.f;
    for (int r = 0; r < 8; r++)
        #pragma unroll
        for (int q = 0; q < 8; q++) {
            int n = (ph*8 + r) * 64 + pw*8 + q;
            s += g_xs[(size_t)(b*NTOK + n)*CC + c];
        }
    float avg = s * (1.f/64.f);

    float v1 = avg, v2 = avg*avg;
    #pragma unroll
    for (int o = 16; o; o >>= 1) {
        v1 += __shfl_xor_sync(0xffffffffu, v1, o);
        v2 += __shfl_xor_sync(0xffffffffu, v2, o);
    }
    __shared__ float s1[8], s2[8];
    int w = c >> 5, lane = c & 31;
    if (lane == 0) { s1[w] = v1; s2[w] = v2; }
    __syncthreads();
    float m1 = 0.f, m2 = 0.f;
    #pragma unroll
    for (int ww = 0; ww < 8; ww++) { m1 += s1[ww]; m2 += s2[ww]; }
    m1 *= (1.f/256.f); m2 *= (1.f/256.f);
    float var = m2 - m1*m1;
    g_pln[bp*CC + c] = (avg - m1) * rsqrtf(var + 1e-5f) * ng[c] + nb[c];
}

// ---------------- pooled kv projection + k_pool l2norm ----------------
__global__ void kvpool_kernel(const float* __restrict__ kv_w,
                              const float* __restrict__ kv_b)
{
    int bp = blockIdx.x; int b = bp >> 6, p = bp & 63;
    __shared__ __align__(16) float xr[CC];
    int tid = threadIdx.x;
    if (tid < CC) xr[tid] = g_pln[bp*CC + tid];
    __syncthreads();

    int o = tid;
    float acc = kv_b[o];
    const float4* w4 = (const float4*)(kv_w + (size_t)o * CC);
    const float4* x4 = (const float4*)xr;
    #pragma unroll 8
    for (int k = 0; k < 64; k++) {
        float4 w = w4[k], xv = x4[k];
        acc += w.x*xv.x + w.y*xv.y + w.z*xv.z + w.w*xv.w;
    }
    int lane = tid & 31;
    if (o < CC) {
        float s = acc*acc;
        #pragma unroll
        for (int q = 16; q; q >>= 1) s += __shfl_xor_sync(0xffffffffu, s, q);
        float kn = acc / fmaxf(sqrtf(s), 1e-12f);
        int h = o >> 5;
        g_kpT[((b*NHH + h)*HDD + lane)*PP + p] = kn;
    } else {
        int oo = o - CC; int h = oo >> 5, d = oo & 31;
        g_vpl[((b*NHH + h)*PP + p)*HDD + d] = acc;
    }
}

// ---------------- CPB MLP ----------------
__global__ void cpb_kernel(const float* __restrict__ table,
                           const float* __restrict__ w1, const float* __restrict__ b1,
                           const float* __restrict__ w2, const float* __restrict__ b2)
{
    __shared__ float sw1[1024], sb1[512], sw2[4096];
    int tid = threadIdx.x;
    for (int i = tid; i < 1024; i += 128) sw1[i] = w1[i];
    for (int i = tid; i <  512; i += 128) sb1[i] = b1[i];
    for (int i = tid; i < 4096; i += 128) sw2[i] = w2[i];
    __syncthreads();

    int t = blockIdx.x * 128 + tid;
    float c0 = table[2*t], c1 = table[2*t+1];
    float acc[NHH];
    #pragma unroll
    for (int h = 0; h < NHH; h++) acc[h] = b2[h];
    for (int j = 0; j < 512; j++) {
        float hj = fmaxf(fmaf(c0, sw1[2*j], fmaf(c1, sw1[2*j+1], sb1[j])), 0.f);
        #pragma unroll
        for (int h = 0; h < NHH; h++) acc[h] = fmaf(hj, sw2[h*512 + j], acc[h]);
    }
    #pragma unroll
    for (int h = 0; h < NHH; h++) g_cpb[t*NHH + h] = acc[h];
}

// ---------------- pool bias gather ----------------
__global__ void pbias_kernel(const int* __restrict__ rpi)
{
    int n = blockIdx.x, tid = threadIdx.x;
    int h = tid >> 6, p = tid & 63;
    int r = rpi[n*PP + p];
    g_pb[(size_t)n*512 + tid] = g_cpb[r*NHH + h];
}

// ---------------- fused attention v2: head-pair blocks, front-loaded memory ----------------
__global__ __launch_bounds__(256, 4) void attn_kernel2(
    const float* __restrict__ rpb_g, const float* __restrict__ lt_g,
    const float* __restrict__ lb_g)
{
    __shared__ __align__(16) float kpT[2*HDD*PP];   // [hh][d][p]   16KB
    __shared__ __align__(16) float vpl[2*PP*HDD];   // [hh][p][d]   16KB
    __shared__ float lts[2*HDD*LL];                 // [hh][lane][l]
    __shared__ float rpbs[2*LL], lbs[2*LL];
    __shared__ float qbuf[8*32], apb[8*64];

    const int tid = threadIdx.x;
    const int b = blockIdx.y >> 2, hp = blockIdx.y & 3, chunk = blockIdx.x;
    const int h0 = hp * 2;

    for (int i = tid; i < 1024; i += 256) {
        ((float4*)kpT)[i] = ((const float4*)(g_kpT + (size_t)(b*NHH + h0)*2048))[i];
        ((float4*)vpl)[i] = ((const float4*)(g_vpl + (size_t)(b*NHH + h0)*2048))[i];
    }
    for (int i = tid; i < 2*HDD*LL; i += 256) lts[i] = lt_g[h0*HDD*LL + i];
    if (tid < 2*LL) { rpbs[tid] = rpb_g[h0*LL + tid]; lbs[tid] = lb_g[h0*LL + tid]; }
    __syncthreads();

    const int w = tid >> 5, lane = tid & 31;
    const int hh = w & 1, sub = w >> 1;
    const int h = h0 + hh;
    const float* kh  = kpT + hh * (HDD*PP);
    const float* vh  = vpl + hh * (PP*HDD);
    const float* lth = lts + hh * (HDD*LL);

    for (int t = 0; t < 32; t++) {
        int n = chunk*128 + t*4 + sub;
        int i = n >> 6, j = n & 63;
        size_t base = (size_t)(b*NTOK + n)*CC + h*HDD + lane;

        float qsc = g_qs[base];
        float qnv = g_qn[base];
        qbuf[w*32 + lane] = qsc;
        __syncwarp();

        // front-load ALL gmem: neighbors' kn AND v + pool bias
        float kvv[LL], vvv[LL];
        bool  vlm[LL];
        #pragma unroll
        for (int l = 0; l < LL; l++) {
            int ii = i + l/3 - 1, jj = j + l%3 - 1;
            vlm[l] = ((unsigned)ii < 64u) && ((unsigned)jj < 64u);
            size_t off = (size_t)(b*NTOK + ii*64 + jj)*CC + h*HDD + lane;
            kvv[l] = vlm[l] ? g_kn[off] : 0.f;
            vvv[l] = vlm[l] ? g_v [off] : 0.f;
        }
        float pb0 = g_pb[(size_t)n*512 + h*64 + lane];
        float pb1 = g_pb[(size_t)n*512 + h*64 + lane + 32];

        // pool logits (lane = p, p+32)
        float pl0 = 0.f, pl1 = 0.f;
        #pragma unroll
        for (int d = 0; d < 32; d++) {
            float qd = qbuf[w*32 + d];
            pl0 = fmaf(qd, kh[d*64 + lane],      pl0);
            pl1 = fmaf(qd, kh[d*64 + lane + 32], pl1);
        }
        pl0 += pb0; pl1 += pb1;

        // local logits + learnable-token dots (butterfly reductions)
        float el[LL], alt[LL];
        #pragma unroll
        for (int l = 0; l < LL; l++) {
            float s = qsc * kvv[l];
            float a = qnv * lth[lane*LL + l];
            #pragma unroll
            for (int o = 16; o; o >>= 1) {
                s += __shfl_xor_sync(0xffffffffu, s, o);
                a += __shfl_xor_sync(0xffffffffu, a, o);
            }
            el [l] = vlm[l] ? (s + rpbs[hh*LL + l]) : -1e30f;
            alt[l] = a + lbs[hh*LL + l];
        }

        // joint softmax over 9 local (replicated) + 64 pool (lane-distributed)
        float m = fmaxf(pl0, pl1);
        #pragma unroll
        for (int l = 0; l < LL; l++) m = fmaxf(m, el[l]);
        #pragma unroll
        for (int o = 16; o; o >>= 1) m = fmaxf(m, __shfl_xor_sync(0xffffffffu, m, o));
        float ls = 0.f;
        #pragma unroll
        for (int l = 0; l < LL; l++) { el[l] = __expf(el[l] - m); ls += el[l]; }
        float e0 = __expf(pl0 - m), e1 = __expf(pl1 - m);
        float ps = e0 + e1;
        #pragma unroll
        for (int o = 16; o; o >>= 1) ps += __shfl_xor_sync(0xffffffffu, ps, o);
        float inv = 1.f / (ls + ps);

        // local output (vvv = 0 at padded taps -> no mask needed)
        float xo = 0.f;
        #pragma unroll
        for (int l = 0; l < LL; l++)
            xo = fmaf(el[l]*inv + alt[l], vvv[l], xo);

        // pool output
        apb[w*64 + lane]      = e0 * inv;
        apb[w*64 + 32 + lane] = e1 * inv;
        __syncwarp();
        #pragma unroll 8
        for (int p = 0; p < 64; p++)
            xo = fmaf(apb[w*64 + p], vh[p*32 + lane], xo);

        // write bf16 hi/lo directly for the proj GEMM
        __nv_bfloat16 hv = __float2bfloat16(xo);
        g_ath[base] = hv;
        g_atl[base] = __float2bfloat16(xo - __bfloat162float(hv));
        __syncwarp();
    }
}

// ---------------- launch ----------------
extern "C" void kernel_launch(void* const* d_in, const int* in_sizes, int n_in,
                              void* d_out, int out_size)
{
    const float* x      = (const float*)d_in[0];
    const int*   rpi    = (const int*)  d_in[1];
    const float* table  = (const float*)d_in[2];
    const float* q_w    = (const float*)d_in[3];
    const float* q_b    = (const float*)d_in[4];
    const float* kv_w   = (const float*)d_in[5];
    const float* kv_b   = (const float*)d_in[6];
    const float* temp   = (const float*)d_in[7];
    const float* qe     = (const float*)d_in[8];
    const float* proj_w = (const float*)d_in[9];
    const float* proj_b = (const float*)d_in[10];
    const float* sr_w   = (const float*)d_in[11];
    const float* sr_b   = (const float*)d_in[12];
    const float* norm_g = (const float*)d_in[13];
    const float* norm_b = (const float*)d_in[14];
    const float* cpb1_w = (const float*)d_in[15];
    const float* cpb1_b = (const float*)d_in[16];
    const float* cpb2_w = (const float*)d_in[17];
    const float* cpb2_b = (const float*)d_in[18];
    const float* rpb    = (const float*)d_in[19];
    const float* lt     = (const float*)d_in[20];
    const float* lb     = (const float*)d_in[21];
    const float* sls    = (const float*)d_in[22];
    float* out = (float*)d_out;

    void *p_qraw, *p_kvraw, *p_xs;
    void *p_xh, *p_xl, *p_ath, *p_atl;
    void *p_qwh, *p_qwl, *p_kwh, *p_kwl, *p_swh, *p_swl, *p_pwh, *p_pwl;
    cudaGetSymbolAddress(&p_qraw,  g_qraw);
    cudaGetSymbolAddress(&p_kvraw, g_kvraw);
    cudaGetSymbolAddress(&p_xs,    g_xs);
    cudaGetSymbolAddress(&p_xh,  g_xh);  cudaGetSymbolAddress(&p_xl,  g_xl);
    cudaGetSymbolAddress(&p_ath, g_ath); cudaGetSymbolAddress(&p_atl, g_atl);
    cudaGetSymbolAddress(&p_qwh, g_qwh); cudaGetSymbolAddress(&p_qwl, g_qwl);
    cudaGetSymbolAddress(&p_kwh, g_kwh); cudaGetSymbolAddress(&p_kwl, g_kwl);
    cudaGetSymbolAddress(&p_swh, g_swh); cudaGetSymbolAddress(&p_swl, g_swl);
    cudaGetSymbolAddress(&p_pwh, g_pwh); cudaGetSymbolAddress(&p_pwl, g_pwl);

    const int M = BB * NTOK;
    const int NX = M * CC;

    cudaFuncSetAttribute(gemm_mma, cudaFuncAttributeMaxDynamicSharedMemorySize, GS_TOT);

    #define BF(p) ((__nv_bfloat16*)(p))
    cvt_hilo<<<(NX+255)/256, 256>>>(x, BF(p_xh), BF(p_xl), NX);
    cvt_hilo<<<(CC*CC+255)/256, 256>>>(q_w,  BF(p_qwh), BF(p_qwl), CC*CC);
    cvt_hilo<<<(2*CC*CC+255)/256, 256>>>(kv_w, BF(p_kwh), BF(p_kwl), 2*CC*CC);
    gemm_mma<<<dim3(4, M/128), 256, GS_TOT>>>(BF(p_xh), BF(p_xl), BF(p_kwh), BF(p_kwl),
                                              kv_b, (float*)p_kvraw, 2*CC, 0);
    cvt_hilo<<<(CC*CC+255)/256, 256>>>(sr_w,   BF(p_swh), BF(p_swl), CC*CC);
    cvt_hilo<<<(CC*CC+255)/256, 256>>>(proj_w, BF(p_pwh), BF(p_pwl), CC*CC);
    gemm_mma<<<dim3(2, M/128), 256, GS_TOT>>>(BF(p_xh), BF(p_xl), BF(p_qwh), BF(p_qwl),
                                              q_b, (float*)p_qraw, CC, 0);
    gemm_mma<<<dim3(2, M/128), 256, GS_TOT>>>(BF(p_xh), BF(p_xl), BF(p_swh), BF(p_swl),
                                              sr_b, (float*)p_xs, CC, 1);

    normalize_kernel<<<M, CC>>>(qe, temp, sls);
    pool_ln_kernel<<<BB*PP, CC>>>(norm_g, norm_b);
    kvpool_kernel<<<BB*PP, 512>>>(kv_w, kv_b);
    cpb_kernel<<<TT/128, 128>>>(table, cpb1_w, cpb1_b, cpb2_w, cpb2_b);
    pbias_kernel<<<NTOK, 512>>>(rpi);

    attn_kernel2<<<dim3(32, 16), 256>>>(rpb, lt, lb);

    gemm_mma<<<dim3(2, M/128), 256, GS_TOT>>>(BF(p_ath), BF(p_atl), BF(p_pwh), BF(p_pwl),
                                              proj_b, out, CC, 0);
    #undef BF
}